// round 1
// baseline (speedup 1.0000x reference)
#include <cuda_runtime.h>
#include <math.h>

#define DEV_INLINE __device__ __forceinline__

// Problem constants
constexpr int Bc = 4, Tc = 200, Uc = 100, U1 = 101, Hc = 320, IN = 512, Vc = 1000;
constexpr int ROWS_B = Tc * U1;                    // 20200 rows (t,u) per batch
constexpr int MT = 64, NTILE = 128, KT = 64;
constexpr int NTILES = (Vc + NTILE - 1) / NTILE;   // 8
constexpr int KTILES = IN / KT;                    // 8
constexpr int BLKS_B = (ROWS_B + MT - 1) / MT;     // 316
constexpr int SMEM_JOINT = (MT * IN + KT * NTILE) * (int)sizeof(float); // 163840 B

// Scratch (no allocations allowed -> device globals)
__device__ float g_henc[Bc * Tc * IN];
__device__ float g_hdec[Bc * U1 * IN];
__device__ float g_blank[Bc * Tc * U1];
__device__ float g_label[Bc * Tc * Uc];

DEV_INLINE float tanh_approx(float x) {
    float y;
    asm("tanh.approx.f32 %0, %1;" : "=f"(y) : "f"(x));
    return y;
}

// ---------------------------------------------------------------------------
// Kernel 1: h_enc = enc @ W1[:H] + b1 ; h_dec = dec @ W1[H:]
// One block = 8 rows. 128 threads, each computes 8 rows x 4 cols.
// ---------------------------------------------------------------------------
constexpr int M2 = 8;
constexpr int ENC_BLKS = (Bc * Tc) / M2;           // 100
constexpr int DEC_BLKS = (Bc * U1 + M2 - 1) / M2;  // 51

__global__ __launch_bounds__(128) void proj_kernel(
    const float* __restrict__ enc, const float* __restrict__ dec,
    const float* __restrict__ W1, const float* __restrict__ b1) {
    __shared__ float x_s[M2][Hc];
    const int blk = blockIdx.x;
    const bool is_enc = blk < ENC_BLKS;
    const int r0 = (is_enc ? blk : blk - ENC_BLKS) * M2;
    const int nrows = is_enc ? Bc * Tc : Bc * U1;
    const float* __restrict__ X = is_enc ? enc : dec;
    float* __restrict__ Y = is_enc ? g_henc : g_hdec;
    const int woff = is_enc ? 0 : Hc;

    for (int idx = threadIdx.x; idx < M2 * Hc; idx += 128) {
        int r = idx / Hc, i = idx - r * Hc;
        x_s[r][i] = (r0 + r < nrows) ? X[(size_t)(r0 + r) * Hc + i] : 0.f;
    }
    __syncthreads();

    const int i0 = threadIdx.x;
    float acc[M2][4];
#pragma unroll
    for (int j = 0; j < 4; ++j) {
        float bv = is_enc ? b1[i0 + j * 128] : 0.f;
#pragma unroll
        for (int r = 0; r < M2; ++r) acc[r][j] = bv;
    }
    for (int h = 0; h < Hc; ++h) {
        const float* wrow = &W1[(size_t)(woff + h) * IN + i0];
        float w0 = wrow[0], w1 = wrow[128], w2 = wrow[256], w3 = wrow[384];
#pragma unroll
        for (int r = 0; r < M2; ++r) {
            float xv = x_s[r][h];
            acc[r][0] = fmaf(xv, w0, acc[r][0]);
            acc[r][1] = fmaf(xv, w1, acc[r][1]);
            acc[r][2] = fmaf(xv, w2, acc[r][2]);
            acc[r][3] = fmaf(xv, w3, acc[r][3]);
        }
    }
#pragma unroll
    for (int r = 0; r < M2; ++r)
        if (r0 + r < nrows) {
#pragma unroll
            for (int j = 0; j < 4; ++j)
                Y[(size_t)(r0 + r) * IN + i0 + j * 128] = acc[r][j];
        }
}

// ---------------------------------------------------------------------------
// Kernel 2 (dominant): fused  tanh(h_enc+h_dec) @ W2 + b2  -> online logsumexp
// emits blank_lp[b,t,u] and label_lp[b,t,u] only (never materializes logits).
// Block: 64 rows x full V. 256 threads; warp w owns rows w*8..w*8+7 so the
// per-row softmax reduction is pure warp shuffles (no smem, no barriers).
// ---------------------------------------------------------------------------
__global__ __launch_bounds__(256, 1) void joint_kernel(
    const float* __restrict__ W2, const float* __restrict__ b2,
    const int* __restrict__ tokens) {
    extern __shared__ float smem[];
    float* h_s = smem;               // [MT][IN]  64*512 f32 = 128 KB
    float* w_s = smem + MT * IN;     // [KT][NTILE] 64*128 f32 = 32 KB

    const int tid = threadIdx.x;
    const int lane = tid & 31;
    const int wid = tid >> 5;        // 0..7
    const int b = blockIdx.x / BLKS_B;
    const int row0 = (blockIdx.x % BLKS_B) * MT;

    // h tile: h = tanh(h_enc[b,t,:] + h_dec[b,u,:])
    for (int idx = tid; idx < MT * IN; idx += 256) {
        int r = idx >> 9;
        int i = idx & (IN - 1);
        int row = row0 + r;
        float v = 0.f;
        if (row < ROWS_B) {
            int t = row / U1, u = row - t * U1;
            v = tanh_approx(g_henc[(size_t)(b * Tc + t) * IN + i] +
                            g_hdec[(size_t)(b * U1 + u) * IN + i]);
        }
        h_s[idx] = v;
    }

    // per-row running softmax state (uniform across the warp after reductions)
    float m[8], sacc[8], bl[8], tk[8];
    int tcol[8];
#pragma unroll
    for (int rr = 0; rr < 8; ++rr) {
        m[rr] = -INFINITY; sacc[rr] = 0.f; bl[rr] = 0.f; tk[rr] = 0.f;
        int row = row0 + wid * 8 + rr;
        int u = row % U1;
        tcol[rr] = (row < ROWS_B && u < Uc) ? tokens[b * Uc + u] : -1;
    }
    __syncthreads();

    for (int nt = 0; nt < NTILES; ++nt) {
        const int n0 = nt * NTILE;
        float bv[4];
#pragma unroll
        for (int cc = 0; cc < 4; ++cc) {
            int col = n0 + lane * 4 + cc;
            bv[cc] = (col < Vc) ? b2[col] : 0.f;
        }
        float acc[8][4];
#pragma unroll
        for (int rr = 0; rr < 8; ++rr)
#pragma unroll
            for (int cc = 0; cc < 4; ++cc) acc[rr][cc] = bv[cc];

        for (int kt = 0; kt < KTILES; ++kt) {
            __syncthreads();   // protect w_s from previous readers
            {
                int col = n0 + lane * 4;
                bool okc = col < Vc;           // col % 4 == 0, Vc % 4 == 0
#pragma unroll
                for (int it = 0; it < 8; ++it) {
                    int krow = it * 8 + wid;
                    float4 w4 = make_float4(0.f, 0.f, 0.f, 0.f);
                    if (okc)
                        w4 = *reinterpret_cast<const float4*>(
                            &W2[(size_t)(kt * KT + krow) * Vc + col]);
                    *reinterpret_cast<float4*>(&w_s[krow * NTILE + lane * 4]) = w4;
                }
            }
            __syncthreads();
            const float* hbase = &h_s[(wid * 8) * IN + kt * KT];
#pragma unroll 4
            for (int k = 0; k < KT; ++k) {
                float4 w4 = *reinterpret_cast<const float4*>(&w_s[k * NTILE + lane * 4]);
#pragma unroll
                for (int rr = 0; rr < 8; ++rr) {
                    float hv = hbase[rr * IN + k];
                    acc[rr][0] = fmaf(hv, w4.x, acc[rr][0]);
                    acc[rr][1] = fmaf(hv, w4.y, acc[rr][1]);
                    acc[rr][2] = fmaf(hv, w4.z, acc[rr][2]);
                    acc[rr][3] = fmaf(hv, w4.w, acc[rr][3]);
                }
            }
        }

        // warp-local online logsumexp update + blank/token capture
#pragma unroll
        for (int rr = 0; rr < 8; ++rr) {
            float lm = -INFINITY;
#pragma unroll
            for (int cc = 0; cc < 4; ++cc) {
                int col = n0 + lane * 4 + cc;
                if (col < Vc) lm = fmaxf(lm, acc[rr][cc]);
            }
#pragma unroll
            for (int o = 16; o > 0; o >>= 1)
                lm = fmaxf(lm, __shfl_xor_sync(0xffffffffu, lm, o));
            float le = 0.f;
#pragma unroll
            for (int cc = 0; cc < 4; ++cc) {
                int col = n0 + lane * 4 + cc;
                if (col < Vc) le += __expf(acc[rr][cc] - lm);
            }
#pragma unroll
            for (int o = 16; o > 0; o >>= 1)
                le += __shfl_xor_sync(0xffffffffu, le, o);

            float nm = fmaxf(m[rr], lm);
            sacc[rr] = sacc[rr] * __expf(m[rr] - nm) + le * __expf(lm - nm);
            m[rr] = nm;

            if (nt == 0) bl[rr] = __shfl_sync(0xffffffffu, acc[rr][0], 0);
            int rel = tcol[rr] - n0;              // uniform across warp
            if (rel >= 0 && rel < NTILE) {
                int q = rel & 3;
                float cand = (q == 0) ? acc[rr][0]
                           : (q == 1) ? acc[rr][1]
                           : (q == 2) ? acc[rr][2] : acc[rr][3];
                tk[rr] = __shfl_sync(0xffffffffu, cand, rel >> 2);
            }
        }
    }

    if (lane == 0) {
#pragma unroll
        for (int rr = 0; rr < 8; ++rr) {
            int row = row0 + wid * 8 + rr;
            if (row < ROWS_B) {
                int t = row / U1, u = row - t * U1;
                float lse = m[rr] + logf(sacc[rr]);
                g_blank[(b * Tc + t) * U1 + u] = bl[rr] - lse;
                if (u < Uc) g_label[(b * Tc + t) * Uc + u] = tk[rr] - lse;
            }
        }
    }
}

// ---------------------------------------------------------------------------
// Kernel 3: RNN-T forward DP over anti-diagonals (wavefront). One block.
// alpha[t][u] = logaddexp(alpha[t-1][u]+blank[t-1][u], alpha[t][u-1]+label[t][u-1])
// Cells on diagonal d = t+u depend only on diagonal d-1 -> rolling buffers.
// ---------------------------------------------------------------------------
__global__ __launch_bounds__(512) void dp_kernel(
    const int* __restrict__ out_len, const int* __restrict__ tok_len,
    float* __restrict__ out) {
    __shared__ float bufA[Bc][U1 + 3];
    __shared__ float bufB[Bc][U1 + 3];
    __shared__ float ll_alpha[Bc];
    __shared__ float ll_final[Bc];

    const int tid = threadIdx.x;
    const int b = tid >> 7;        // 0..3
    const int u = tid & 127;       // 0..127
    const bool ok = (u <= Uc);
    const int tl = out_len[b];
    const int ul = tok_len[b];

    float* prev = bufA[b];
    float* cur = bufB[b];

    float cbl = 0.f, clb = 0.f;    // lp values for current diagonal (prefetched)

    for (int d = 0; d <= (Tc - 1) + Uc; ++d) {
        // prefetch global loads for diagonal d+1 (independent of prev/cur)
        float nbl = 0.f, nlb = 0.f;
        {
            int tn = (d + 1) - u;
            if (ok && tn >= 1 && tn < Tc) nbl = g_blank[(b * Tc + (tn - 1)) * U1 + u];
            if (ok && u >= 1 && tn >= 0 && tn < Tc) nlb = g_label[(b * Tc + tn) * Uc + (u - 1)];
        }
        int t = d - u;
        if (ok && t >= 0 && t < Tc) {
            float val;
            if (d == 0) {
                val = 0.f;  // alpha[0][0]
            } else {
                float x = (t >= 1) ? prev[u] + cbl : -INFINITY;
                float y = (u >= 1) ? prev[u - 1] + clb : -INFINITY;
                float hi = fmaxf(x, y), lo = fminf(x, y);
                val = (lo == -INFINITY) ? hi : hi + log1pf(expf(lo - hi));
            }
            cur[u] = val;
            if (t == tl - 1 && u == ul) ll_alpha[b] = val;
        }
        __syncthreads();
        float* tmp = prev; prev = cur; cur = tmp;
        cbl = nbl; clb = nlb;
    }

    if (u == 0)
        ll_final[b] = ll_alpha[b] + g_blank[(b * Tc + (tl - 1)) * U1 + ul];
    __syncthreads();
    if (tid == 0) {
        float s = 0.f;
        for (int i = 0; i < Bc; ++i) s += ll_final[i];
        out[0] = -s / (float)Bc;
    }
}

// ---------------------------------------------------------------------------
extern "C" void kernel_launch(void* const* d_in, const int* in_sizes, int n_in,
                              void* d_out, int out_size) {
    const float* enc     = (const float*)d_in[0];
    const float* dec     = (const float*)d_in[1];
    const int*   tokens  = (const int*)d_in[2];
    const int*   out_len = (const int*)d_in[3];
    const int*   tok_len = (const int*)d_in[4];
    const float* W1      = (const float*)d_in[5];
    const float* b1      = (const float*)d_in[6];
    const float* W2      = (const float*)d_in[7];
    const float* b2      = (const float*)d_in[8];
    float* out = (float*)d_out;

    cudaFuncSetAttribute(joint_kernel, cudaFuncAttributeMaxDynamicSharedMemorySize,
                         SMEM_JOINT);

    proj_kernel<<<ENC_BLKS + DEC_BLKS, 128>>>(enc, dec, W1, b1);
    joint_kernel<<<Bc * BLKS_B, 256, SMEM_JOINT>>>(W2, b2, tokens);
    dp_kernel<<<1, 512>>>(out_len, tok_len, out);
}

// round 3
// speedup vs baseline: 4.6283x; 4.6283x over previous
#include <cuda_runtime.h>
#include <cuda_bf16.h>
#include <math.h>
#include <stdint.h>

#define DEV_INLINE __device__ __forceinline__

// Problem constants
constexpr int Bc = 4, Tc = 200, Uc = 100, U1 = 101, Hc = 320, IN = 512, Vc = 1000;
constexpr int ROWS_B = Tc * U1;                    // 20200 rows (t,u) per batch
constexpr int MT = 128;                            // rows per CTA
constexpr int VPAD = 1024;                         // V padded to 8x128
constexpr int BLKS_B = (ROWS_B + MT - 1) / MT;     // 158

constexpr int AS = 520;                            // A smem stride (bf16 elems)
constexpr int BS = 72;                             // B smem stride (bf16 elems)
constexpr int A_BYTES = MT * AS * 2;               // 133120
constexpr int B_BYTES = 128 * BS * 2;              // 18432
constexpr int DSMEM = A_BYTES + 2 * B_BYTES;       // 169984

// Scratch (no allocations allowed -> device globals)
__device__ __align__(16) float g_henc[Bc * Tc * IN];
__device__ __align__(16) float g_hdec[Bc * U1 * IN];
__device__ __align__(16) __nv_bfloat16 g_W2t[VPAD * IN];   // W2^T [v][k], bf16
__device__ float g_blank[Bc * Tc * U1];
__device__ float g_label[Bc * Tc * Uc];
__device__ float g_ll[Bc];

// ---------------------------------------------------------------------------
// Helpers
// ---------------------------------------------------------------------------
DEV_INLINE float tanh_approx(float x) {
    float y; asm("tanh.approx.f32 %0, %1;" : "=f"(y) : "f"(x)); return y;
}
DEV_INLINE uint32_t smemu32(const void* p) {
    uint32_t a;
    asm("{ .reg .u64 t; cvta.to.shared.u64 t, %1; cvt.u32.u64 %0, t; }" : "=r"(a) : "l"(p));
    return a;
}
DEV_INLINE void cp_async16(uint32_t dst, const void* src) {
    asm volatile("cp.async.ca.shared.global [%0], [%1], 16;"
                 :: "r"(dst), "l"(src) : "memory");
}
DEV_INLINE void cp_commit() { asm volatile("cp.async.commit_group;" ::: "memory"); }
DEV_INLINE void cp_wait1()  { asm volatile("cp.async.wait_group 1;" ::: "memory"); }
DEV_INLINE void cp_wait0()  { asm volatile("cp.async.wait_group 0;" ::: "memory"); }

DEV_INLINE void ldmx4(uint32_t addr, uint32_t& r0, uint32_t& r1, uint32_t& r2, uint32_t& r3) {
    asm volatile("ldmatrix.sync.aligned.m8n8.x4.shared.b16 {%0,%1,%2,%3}, [%4];"
                 : "=r"(r0), "=r"(r1), "=r"(r2), "=r"(r3) : "r"(addr));
}
DEV_INLINE void mma_bf16(float& c0, float& c1, float& c2, float& c3,
                         uint32_t a0, uint32_t a1, uint32_t a2, uint32_t a3,
                         uint32_t b0, uint32_t b1) {
    asm volatile(
        "mma.sync.aligned.m16n8k16.row.col.f32.bf16.bf16.f32 "
        "{%0,%1,%2,%3}, {%4,%5,%6,%7}, {%8,%9}, {%0,%1,%2,%3};"
        : "+f"(c0), "+f"(c1), "+f"(c2), "+f"(c3)
        : "r"(a0), "r"(a1), "r"(a2), "r"(a3), "r"(b0), "r"(b1));
}

// ---------------------------------------------------------------------------
// Kernel 0: W2 [512][1000] fp32 -> g_W2t [1024][512] bf16 (transpose + pad 0)
// ---------------------------------------------------------------------------
__global__ __launch_bounds__(256) void w2prep(const float* __restrict__ W2) {
    __shared__ float tile[32][33];
    const int kb = blockIdx.x * 32, vb = blockIdx.y * 32;
    const int tx = threadIdx.x & 31, ty = threadIdx.x >> 5;
#pragma unroll
    for (int i = 0; i < 4; ++i) {
        int k = kb + ty + 8 * i, v = vb + tx;
        tile[ty + 8 * i][tx] = (v < Vc) ? W2[(size_t)k * Vc + v] : 0.f;
    }
    __syncthreads();
#pragma unroll
    for (int i = 0; i < 4; ++i) {
        int v = vb + ty + 8 * i, k = kb + tx;
        g_W2t[(size_t)v * IN + k] = __float2bfloat16(tile[tx][ty + 8 * i]);
    }
}

// ---------------------------------------------------------------------------
// Kernel 1: projections  h_enc = enc @ W1[:H] + b1 ; h_dec = dec @ W1[H:]
// ---------------------------------------------------------------------------
constexpr int ENC_BLKS = (Bc * Tc) / 8;            // 100
constexpr int DEC_BLKS = (Bc * U1 + 7) / 8;        // 51

__global__ __launch_bounds__(128) void proj_kernel(
    const float* __restrict__ enc, const float* __restrict__ dec,
    const float* __restrict__ W1, const float* __restrict__ b1) {
    __shared__ float x_s[8][Hc];
    const int blk = blockIdx.x;
    const bool is_enc = blk < ENC_BLKS;
    const int r0 = (is_enc ? blk : blk - ENC_BLKS) * 8;
    const int nrows = is_enc ? Bc * Tc : Bc * U1;
    const float* __restrict__ X = is_enc ? enc : dec;
    float* __restrict__ Y = is_enc ? g_henc : g_hdec;
    const int woff = is_enc ? 0 : Hc;
    const int col = blockIdx.y * 128 + threadIdx.x;

    for (int idx = threadIdx.x; idx < 8 * Hc; idx += 128) {
        int r = idx / Hc, i = idx - r * Hc;
        x_s[r][i] = (r0 + r < nrows) ? X[(size_t)(r0 + r) * Hc + i] : 0.f;
    }
    __syncthreads();

    float acc[8];
    const float bv = is_enc ? b1[col] : 0.f;
#pragma unroll
    for (int r = 0; r < 8; ++r) acc[r] = bv;
#pragma unroll 4
    for (int h = 0; h < Hc; ++h) {
        float w = W1[(size_t)(woff + h) * IN + col];
#pragma unroll
        for (int r = 0; r < 8; ++r) acc[r] = fmaf(x_s[r][h], w, acc[r]);
    }
#pragma unroll
    for (int r = 0; r < 8; ++r)
        if (r0 + r < nrows) Y[(size_t)(r0 + r) * IN + col] = acc[r];
}

// ---------------------------------------------------------------------------
// Kernel 2 (dominant): mma.sync bf16 joint GEMM + fused online logsumexp.
//   A = tanh(henc+hdec) [128 x 512] bf16 in SMEM (stride 520, conflict-free)
//   B = W2t chunks [128 n x 64 k] bf16, cp.async double-buffered
//   C = 128 x 128 fp32 in registers per n-tile; epilogue -> running logsumexp.
// 256 threads = 8 warps laid out 4(m) x 2(n); warp tile 32 x 64.
// ---------------------------------------------------------------------------
__global__ __launch_bounds__(256, 1) void joint_mma(
    const float* __restrict__ b2, const int* __restrict__ tokens) {
    extern __shared__ char dsm[];
    __shared__ float b2s[VPAD];
    __shared__ float cm[2][MT], cs[2][MT], ctk[2][MT], cbl[MT];

    const int tid = threadIdx.x;
    const int lane = tid & 31, wid = tid >> 5;
    const int warp_m = wid >> 1, warp_n = wid & 1;
    const int qr = lane >> 2, qc = lane & 3;
    const int b = blockIdx.x / BLKS_B;
    const int row0 = (blockIdx.x % BLKS_B) * MT;

    const uint32_t a_base = smemu32(dsm);
    const uint32_t b_base = a_base + A_BYTES;

    for (int i = tid; i < VPAD; i += 256) b2s[i] = (i < Vc) ? b2[i] : -INFINITY;

    // prologue: issue B chunk 0
    {
#pragma unroll
        for (int q = 0; q < 4; ++q) {
            int i = tid * 4 + q;
            int n = i >> 3, kk8 = (i & 7) * 8;
            cp_async16(b_base + (uint32_t)(n * BS + kk8) * 2,
                       g_W2t + (size_t)n * IN + kk8);
        }
        cp_commit();
    }

    // ---- build A tile: h = tanh(henc[t] + hdec[u]) in bf16 ----
#pragma unroll 2
    for (int r = 0; r < MT; ++r) {
        int row = row0 + r;
        float2 hv = make_float2(0.f, 0.f);
        if (row < ROWS_B) {
            int t = row / U1, u = row - t * U1;
            float2 e = ((const float2*)(g_henc + (size_t)(b * Tc + t) * IN))[tid];
            float2 d = ((const float2*)(g_hdec + (size_t)(b * U1 + u) * IN))[tid];
            hv.x = tanh_approx(e.x + d.x);
            hv.y = tanh_approx(e.y + d.y);
        }
        *(__nv_bfloat162*)(dsm + r * (AS * 2) + tid * 4) = __float22bfloat162_rn(hv);
    }

    // per-slot (4 rows/thread) running logsumexp state
    float m4[4], s4[4], tk4[4], bl4[4];
    int rowloc[4], tcol4[4];
#pragma unroll
    for (int s = 0; s < 4; ++s) {
        m4[s] = -INFINITY; s4[s] = 0.f; tk4[s] = -INFINITY; bl4[s] = -INFINITY;
        rowloc[s] = warp_m * 32 + (s >> 1) * 16 + (s & 1) * 8 + qr;
        int row = row0 + rowloc[s];
        int u = row % U1;
        tcol4[s] = (row < ROWS_B && u < Uc) ? tokens[b * Uc + u] : -1;
    }

    // ldmatrix lane-address offsets
    const int a_row_off = (lane & 7) + ((lane >> 3) & 1) * 8;
    const int a_k_off = (lane >> 4) * 8;
    const int b_n_off = (lane & 7) + ((lane >> 4) & 1) * 8;
    const int b_k_off = ((lane >> 3) & 1) * 8;
    const uint32_t a_addr0 =
        a_base + (uint32_t)((warp_m * 32 + a_row_off) * AS + a_k_off) * 2;
    const uint32_t b_addr0 =
        b_base + (uint32_t)((warp_n * 64 + b_n_off) * BS + b_k_off) * 2;

    float acc[2][8][4];

    for (int ch = 0; ch < 64; ++ch) {          // 8 ntiles x 8 kchunks of 64
        const int buf = ch & 1;
        const int nt = ch >> 3, kc = ch & 7;

        if (ch + 1 < 64) {                      // issue next chunk
            int nn = (ch + 1) >> 3, nk = (ch + 1) & 7;
            const __nv_bfloat16* src0 = g_W2t + (size_t)(nn * 128) * IN + nk * 64;
            uint32_t dst0 = b_base + ((ch + 1) & 1) * B_BYTES;
#pragma unroll
            for (int q = 0; q < 4; ++q) {
                int i = tid * 4 + q;
                int n = i >> 3, kk8 = (i & 7) * 8;
                cp_async16(dst0 + (uint32_t)(n * BS + kk8) * 2,
                           src0 + (size_t)n * IN + kk8);
            }
            cp_commit();
            cp_wait1();
        } else {
            cp_wait0();
        }
        __syncthreads();

        if (kc == 0) {
#pragma unroll
            for (int mi = 0; mi < 2; ++mi)
#pragma unroll
                for (int nf = 0; nf < 8; ++nf)
#pragma unroll
                    for (int r = 0; r < 4; ++r) acc[mi][nf][r] = 0.f;
        }

        const uint32_t bb = b_addr0 + buf * B_BYTES;
#pragma unroll
        for (int kk = 0; kk < 64; kk += 16) {
            uint32_t a[2][4], bfrg[4][4];
#pragma unroll
            for (int mi = 0; mi < 2; ++mi)
                ldmx4(a_addr0 + (uint32_t)(mi * 16 * AS + kc * 64 + kk) * 2,
                      a[mi][0], a[mi][1], a[mi][2], a[mi][3]);
#pragma unroll
            for (int ng = 0; ng < 4; ++ng)
                ldmx4(bb + (uint32_t)(ng * 16 * BS + kk) * 2,
                      bfrg[ng][0], bfrg[ng][1], bfrg[ng][2], bfrg[ng][3]);
#pragma unroll
            for (int mi = 0; mi < 2; ++mi)
#pragma unroll
                for (int nf = 0; nf < 8; ++nf) {
                    int ng = nf >> 1, pr = (nf & 1) * 2;
                    mma_bf16(acc[mi][nf][0], acc[mi][nf][1],
                             acc[mi][nf][2], acc[mi][nf][3],
                             a[mi][0], a[mi][1], a[mi][2], a[mi][3],
                             bfrg[ng][pr], bfrg[ng][pr + 1]);
                }
        }
        __syncthreads();   // done reading buf before it is overwritten

        if (kc == 7) {
            // ---- epilogue for n-tile nt: update running logsumexp ----
            const int gbase = nt * 128 + warp_n * 64;
#pragma unroll
            for (int s = 0; s < 4; ++s) {
                const int mi = s >> 1, hf = (s & 1) * 2;
                float v[16], mc = -INFINITY;
#pragma unroll
                for (int nf = 0; nf < 8; ++nf) {
#pragma unroll
                    for (int j = 0; j < 2; ++j) {
                        float x = acc[mi][nf][hf + j] + b2s[gbase + nf * 8 + qc * 2 + j];
                        v[nf * 2 + j] = x;
                        mc = fmaxf(mc, x);
                    }
                }
                float nm = fmaxf(m4[s], mc);
                float add = 0.f;
#pragma unroll
                for (int i = 0; i < 16; ++i) add += __expf(v[i] - nm);
                s4[s] = s4[s] * __expf(m4[s] - nm) + add;
                m4[s] = nm;
                if (nt == 0 && warp_n == 0 && qc == 0) bl4[s] = v[0];
                int rel = tcol4[s] - gbase;
                if (rel >= 0 && rel < 64 && (rel & 7) >> 1 == qc)
                    tk4[s] = v[(rel >> 3) * 2 + (rel & 1)];
            }
        }
    }

    // quad reduction (lanes sharing a row)
#pragma unroll
    for (int off = 1; off <= 2; off <<= 1) {
#pragma unroll
        for (int s = 0; s < 4; ++s) {
            float om = __shfl_xor_sync(0xffffffffu, m4[s], off);
            float os = __shfl_xor_sync(0xffffffffu, s4[s], off);
            float ot = __shfl_xor_sync(0xffffffffu, tk4[s], off);
            float ob = __shfl_xor_sync(0xffffffffu, bl4[s], off);
            float nm = fmaxf(m4[s], om);
            s4[s] = s4[s] * __expf(m4[s] - nm) + os * __expf(om - nm);
            m4[s] = nm;
            tk4[s] = fmaxf(tk4[s], ot);
            bl4[s] = fmaxf(bl4[s], ob);
        }
    }
    if (qc == 0) {
#pragma unroll
        for (int s = 0; s < 4; ++s) {
            int r = rowloc[s];
            cm[warp_n][r] = m4[s];
            cs[warp_n][r] = s4[s];
            ctk[warp_n][r] = tk4[s];
            if (warp_n == 0) cbl[r] = bl4[s];
        }
    }
    __syncthreads();

    if (tid < MT) {
        int row = row0 + tid;
        if (row < ROWS_B) {
            float m0 = cm[0][tid], m1 = cm[1][tid];
            float M = fmaxf(m0, m1);
            float S = cs[0][tid] * __expf(m0 - M) + cs[1][tid] * __expf(m1 - M);
            float lse = M + logf(S);
            float tk = fmaxf(ctk[0][tid], ctk[1][tid]);
            int t = row / U1, u = row - t * U1;
            g_blank[(b * Tc + t) * U1 + u] = cbl[tid] - lse;
            if (u < Uc) g_label[(b * Tc + t) * Uc + u] = tk - lse;
        }
    }
}

// ---------------------------------------------------------------------------
// Kernel 3: RNN-T forward DP. One block per batch, lp staged in SMEM.
// ---------------------------------------------------------------------------
constexpr int DP_SMEM = (Tc * U1 + Tc * Uc) * (int)sizeof(float); // 160800

__global__ __launch_bounds__(128) void dp_kernel(
    const int* __restrict__ out_len, const int* __restrict__ tok_len) {
    extern __shared__ float lp[];
    float* blankS = lp;
    float* labelS = lp + Tc * U1;
    __shared__ float bufA[U1 + 1], bufB[U1 + 1];
    __shared__ float llk;

    const int b = blockIdx.x, tid = threadIdx.x;
    for (int i = tid; i < Tc * U1; i += 128) blankS[i] = g_blank[b * Tc * U1 + i];
    for (int i = tid; i < Tc * Uc; i += 128) labelS[i] = g_label[b * Tc * Uc + i];
    const int tl = out_len[b], ul = tok_len[b];
    __syncthreads();

    float* prev = bufA;
    float* cur = bufB;
    const int u = tid;
    const bool ok = (u <= Uc);

    for (int d = 0; d <= (Tc - 1) + Uc; ++d) {
        int t = d - u;
        if (ok && t >= 0 && t < Tc) {
            float val;
            if (d == 0) {
                val = 0.f;
            } else {
                float x = (t >= 1) ? prev[u] + blankS[(t - 1) * U1 + u] : -INFINITY;
                float y = (u >= 1) ? prev[u - 1] + labelS[t * Uc + (u - 1)] : -INFINITY;
                float hi = fmaxf(x, y), lo = fminf(x, y);
                val = (lo == -INFINITY) ? hi : hi + log1pf(__expf(lo - hi));
            }
            cur[u] = val;
            if (t == tl - 1 && u == ul) llk = val;
        }
        __syncthreads();
        float* tmp = prev; prev = cur; cur = tmp;
    }
    if (tid == 0) g_ll[b] = llk + blankS[(tl - 1) * U1 + ul];
}

__global__ void finalize_kernel(float* out) {
    out[0] = -0.25f * (g_ll[0] + g_ll[1] + g_ll[2] + g_ll[3]);
}

// ---------------------------------------------------------------------------
extern "C" void kernel_launch(void* const* d_in, const int* in_sizes, int n_in,
                              void* d_out, int out_size) {
    const float* enc     = (const float*)d_in[0];
    const float* dec     = (const float*)d_in[1];
    const int*   tokens  = (const int*)d_in[2];
    const int*   out_len = (const int*)d_in[3];
    const int*   tok_len = (const int*)d_in[4];
    const float* W1      = (const float*)d_in[5];
    const float* b1      = (const float*)d_in[6];
    const float* W2      = (const float*)d_in[7];
    const float* b2      = (const float*)d_in[8];
    float* out = (float*)d_out;

    cudaFuncSetAttribute(joint_mma, cudaFuncAttributeMaxDynamicSharedMemorySize, DSMEM);
    cudaFuncSetAttribute(dp_kernel, cudaFuncAttributeMaxDynamicSharedMemorySize, DP_SMEM);

    w2prep<<<dim3(IN / 32, VPAD / 32), 256>>>(W2);
    proj_kernel<<<dim3(ENC_BLKS + DEC_BLKS, 4), 128>>>(enc, dec, W1, b1);
    joint_mma<<<Bc * BLKS_B, 256, DSMEM>>>(b2, tokens);
    dp_kernel<<<Bc, 128, DP_SMEM>>>(out_len, tok_len);
    finalize_kernel<<<1, 1>>>(out);
}